// round 8
// baseline (speedup 1.0000x reference)
#include <cuda_runtime.h>

#define HW 192
#define PIX 36864              // 192*192
#define NB 4
#define C_IN 256
#define C_QKV 768
#define C_ATT 512
#define C_OUT 256
#define NWIN_PER_B 2304        // 48*48
#define NWIN 9216

// scratch (allocation-free rule: __device__ globals)
__device__ float g_qkv[(size_t)NB * C_QKV * PIX];
__device__ float g_att[(size_t)NB * C_ATT * PIX];

// ---------------------------------------------------------------------------
// Generic fp32 GEMM over pixels: Y[b][o][p] = sum_k W[o][k] * X[b][k][p]
// BM=64 (o), BN=64 (p), BK=16, 256 threads, 4x4 per-thread tile.
// Optional fused BN epilogue.
// ---------------------------------------------------------------------------
template <int M, int K, bool BN_EP>
__global__ void gemm_kernel(const float* __restrict__ Wm,
                            const float* __restrict__ Xg,
                            float* __restrict__ Yg,
                            const float* __restrict__ gamma,
                            const float* __restrict__ beta,
                            const float* __restrict__ mean,
                            const float* __restrict__ var)
{
    constexpr int BM = 64, BN = 64, BK = 16;
    __shared__ float As[BK][BM];
    __shared__ float Bs[BK][BN];

    const int b  = blockIdx.z;
    const int m0 = blockIdx.y * BM;
    const int n0 = blockIdx.x * BN;
    const float* X = Xg + (size_t)b * K * PIX;
    float*       Y = Yg + (size_t)b * M * PIX;

    const int tid = threadIdx.x;
    const int tx  = tid & 15;   // pixel sub-tile
    const int ty  = tid >> 4;   // channel sub-tile

    const int a_row = tid >> 2;        // m   (0..63)
    const int a_col = (tid & 3) * 4;   // k   (0,4,8,12)
    const int b_row = tid >> 4;        // k   (0..15)
    const int b_col = (tid & 15) * 4;  // n   (0..60)

    float acc[4][4] = {};

    for (int k0 = 0; k0 < K; k0 += BK) {
        float4 av = *(const float4*)&Wm[(size_t)(m0 + a_row) * K + k0 + a_col];
        As[a_col + 0][a_row] = av.x;
        As[a_col + 1][a_row] = av.y;
        As[a_col + 2][a_row] = av.z;
        As[a_col + 3][a_row] = av.w;
        *(float4*)&Bs[b_row][b_col] =
            *(const float4*)&X[(size_t)(k0 + b_row) * PIX + n0 + b_col];
        __syncthreads();

#pragma unroll
        for (int kk = 0; kk < BK; kk++) {
            float4 a4 = *(const float4*)&As[kk][ty * 4];
            float4 b4 = *(const float4*)&Bs[kk][tx * 4];
            float ar[4] = {a4.x, a4.y, a4.z, a4.w};
            float br[4] = {b4.x, b4.y, b4.z, b4.w};
#pragma unroll
            for (int i = 0; i < 4; i++)
#pragma unroll
                for (int j = 0; j < 4; j++)
                    acc[i][j] = fmaf(ar[i], br[j], acc[i][j]);
        }
        __syncthreads();
    }

#pragma unroll
    for (int i = 0; i < 4; i++) {
        const int o = m0 + ty * 4 + i;
        float sc = 1.f, sh = 0.f;
        if (BN_EP) {
            float inv = gamma[o] * rsqrtf(var[o] + 1e-5f);
            sc = inv;
            sh = beta[o] - mean[o] * inv;
        }
        float4 r;
        r.x = acc[i][0] * sc + sh;
        r.y = acc[i][1] * sc + sh;
        r.z = acc[i][2] * sc + sh;
        r.w = acc[i][3] * sc + sh;
        *(float4*)&Y[(size_t)o * PIX + n0 + tx * 4] = r;
    }
}

// ---------------------------------------------------------------------------
// Window attention: one warp per (window, channel-group of 24).
// Half-warp 0 handles the raw head, half-warp 1 the 5x5-avg-pooled head.
// ---------------------------------------------------------------------------
__global__ void attn_kernel(const float* __restrict__ qkv, float* __restrict__ aout)
{
    __shared__ float t [8][24][17];   // raw 24x16 tile per warp (+pad)
    __shared__ float pt[8][24][17];   // pooled tile
    __shared__ float kvs[8][2][72];   // kv[d][m] per (warp, half)

    const int w    = threadIdx.x >> 5;
    const int lane = threadIdx.x & 31;
    const int g0   = blockIdx.y * 8 + w;        // channel-group 0..31
    const int n    = blockIdx.x;                // window id
    const int b    = n / NWIN_PER_B;
    const int rem  = n - b * NWIN_PER_B;
    const int hn   = rem / 48, wn = rem - hn * 48;
    const int pixbase = (hn * 4) * HW + wn * 4;

    const float* src = qkv + (size_t)b * C_QKV * PIX + (size_t)(g0 * 24) * PIX + pixbase;

    const int p    = lane & 15;
    const int r    = p >> 2, c = p & 3;
    const int poff = r * HW + c;
    const int half = lane >> 4;

    // ---- load raw tile: 24 channels x 16 pixels
#pragma unroll
    for (int i = 0; i < 12; i++) {
        const int ch = 2 * i + half;
        t[w][ch][p] = src[(size_t)ch * PIX + poff];
    }
    __syncwarp();

    // ---- 5x5 avg pool (pad 2) inside the 4x4 window
    const int r0 = (r - 2 < 0) ? 0 : r - 2, r1 = (r + 2 > 3) ? 3 : r + 2;
    const int c0 = (c - 2 < 0) ? 0 : c - 2, c1 = (c + 2 > 3) ? 3 : c + 2;
#pragma unroll
    for (int i = 0; i < 12; i++) {
        const int ch = 2 * i + half;
        float s = 0.f;
        for (int rr = r0; rr <= r1; rr++)
            for (int cc = c0; cc <= c1; cc++)
                s += t[w][ch][rr * 4 + cc];
        pt[w][ch][p] = s * (1.0f / 25.0f);
    }
    __syncwarp();

    const float (*tile)[17] = half ? pt[w] : t[w];
    const int lh = lane & 15;

    // ---- kv[d][m] = sum_l relu(k[l][d]) * v[l][m]   (v[:,8] == 1)
    for (int j = lh; j < 72; j += 16) {
        const int d = j / 9, m = j - d * 9;
        float s = 0.f;
#pragma unroll
        for (int pp = 0; pp < 16; pp++) {
            float kd = fmaxf(tile[8 + d][pp], 0.f);
            float vm = (m < 8) ? tile[16 + m][pp] : 1.f;
            s = fmaf(kd, vm, s);
        }
        kvs[w][half][j] = s;
    }
    __syncwarp();

    // ---- out[l][m] = relu(q[l]) . kv[:,m], normalize by m==8 column
    float qv[8];
#pragma unroll
    for (int d = 0; d < 8; d++) qv[d] = fmaxf(tile[d][lh], 0.f);
    float acc[9] = {};
#pragma unroll
    for (int d = 0; d < 8; d++)
#pragma unroll
        for (int m = 0; m < 9; m++)
            acc[m] = fmaf(qv[d], kvs[w][half][d * 9 + m], acc[m]);

    const float inv = 1.f / (acc[8] + 1e-15f);
    const int rr2 = lh >> 2, cc2 = lh & 3;
    float* dst = aout + (size_t)b * C_ATT * PIX
                      + (size_t)(half * 256 + g0 * 8) * PIX
                      + pixbase + rr2 * HW + cc2;
#pragma unroll
    for (int m = 0; m < 8; m++)
        dst[(size_t)m * PIX] = acc[m] * inv;
}

// ---------------------------------------------------------------------------
extern "C" void kernel_launch(void* const* d_in, const int* in_sizes, int n_in,
                              void* d_out, int out_size)
{
    const float* x      = (const float*)d_in[0];
    const float* qkv_w  = (const float*)d_in[1];
    const float* proj_w = (const float*)d_in[2];
    const float* gamma  = (const float*)d_in[3];
    const float* beta   = (const float*)d_in[4];
    const float* mean   = (const float*)d_in[5];
    const float* var    = (const float*)d_in[6];
    float* out = (float*)d_out;

    float* qkvbuf = nullptr;
    float* attbuf = nullptr;
    cudaGetSymbolAddress((void**)&qkvbuf, g_qkv);
    cudaGetSymbolAddress((void**)&attbuf, g_att);

    // K1: qkv = W_qkv * x      (M=768, K=256)
    gemm_kernel<C_QKV, C_IN, false>
        <<<dim3(PIX / 64, C_QKV / 64, NB), 256>>>(qkv_w, x, qkvbuf,
                                                  nullptr, nullptr, nullptr, nullptr);

    // K2: window lite-MSA (raw + pooled heads)
    attn_kernel<<<dim3(NWIN, 4), 256>>>(qkvbuf, attbuf);

    // K3: y = W_proj * att, fused BN  (M=256, K=512)
    gemm_kernel<C_OUT, C_ATT, true>
        <<<dim3(PIX / 64, C_OUT / 64, NB), 256>>>(proj_w, attbuf, out,
                                                  gamma, beta, mean, var);
}

// round 9
// speedup vs baseline: 1.0029x; 1.0029x over previous
#include <cuda_runtime.h>

#define HW 192
#define PIX 36864              // 192*192
#define NB 4
#define C_IN 256
#define C_QKV 768
#define C_ATT 512
#define C_OUT 256
#define NWIN_PER_B 2304        // 48*48
#define NWIN 9216

// scratch (allocation-free rule: __device__ globals)
__device__ float g_qkv[(size_t)NB * C_QKV * PIX];
__device__ float g_att[(size_t)NB * C_ATT * PIX];

// ---------------------------------------------------------------------------
// Generic fp32 GEMM over pixels: Y[b][o][p] = sum_k W[o][k] * X[b][k][p]
// BM=64 (o), BN=64 (p), BK=16, 256 threads, 4x4 per-thread tile.
// Optional fused BN epilogue.
// ---------------------------------------------------------------------------
template <int M, int K, bool BN_EP>
__global__ void gemm_kernel(const float* __restrict__ Wm,
                            const float* __restrict__ Xg,
                            float* __restrict__ Yg,
                            const float* __restrict__ gamma,
                            const float* __restrict__ beta,
                            const float* __restrict__ mean,
                            const float* __restrict__ var)
{
    constexpr int BM = 64, BN = 64, BK = 16;
    __shared__ float As[BK][BM];
    __shared__ float Bs[BK][BN];

    const int b  = blockIdx.z;
    const int m0 = blockIdx.y * BM;
    const int n0 = blockIdx.x * BN;
    const float* X = Xg + (size_t)b * K * PIX;
    float*       Y = Yg + (size_t)b * M * PIX;

    const int tid = threadIdx.x;
    const int tx  = tid & 15;   // pixel sub-tile
    const int ty  = tid >> 4;   // channel sub-tile

    const int a_row = tid >> 2;        // m   (0..63)
    const int a_col = (tid & 3) * 4;   // k   (0,4,8,12)
    const int b_row = tid >> 4;        // k   (0..15)
    const int b_col = (tid & 15) * 4;  // n   (0..60)

    float acc[4][4] = {};

    for (int k0 = 0; k0 < K; k0 += BK) {
        float4 av = *(const float4*)&Wm[(size_t)(m0 + a_row) * K + k0 + a_col];
        As[a_col + 0][a_row] = av.x;
        As[a_col + 1][a_row] = av.y;
        As[a_col + 2][a_row] = av.z;
        As[a_col + 3][a_row] = av.w;
        *(float4*)&Bs[b_row][b_col] =
            *(const float4*)&X[(size_t)(k0 + b_row) * PIX + n0 + b_col];
        __syncthreads();

#pragma unroll
        for (int kk = 0; kk < BK; kk++) {
            float4 a4 = *(const float4*)&As[kk][ty * 4];
            float4 b4 = *(const float4*)&Bs[kk][tx * 4];
            float ar[4] = {a4.x, a4.y, a4.z, a4.w};
            float br[4] = {b4.x, b4.y, b4.z, b4.w};
#pragma unroll
            for (int i = 0; i < 4; i++)
#pragma unroll
                for (int j = 0; j < 4; j++)
                    acc[i][j] = fmaf(ar[i], br[j], acc[i][j]);
        }
        __syncthreads();
    }

#pragma unroll
    for (int i = 0; i < 4; i++) {
        const int o = m0 + ty * 4 + i;
        float sc = 1.f, sh = 0.f;
        if (BN_EP) {
            float inv = gamma[o] * rsqrtf(var[o] + 1e-5f);
            sc = inv;
            sh = beta[o] - mean[o] * inv;
        }
        float4 r;
        r.x = acc[i][0] * sc + sh;
        r.y = acc[i][1] * sc + sh;
        r.z = acc[i][2] * sc + sh;
        r.w = acc[i][3] * sc + sh;
        *(float4*)&Y[(size_t)o * PIX + n0 + tx * 4] = r;
    }
}

// ---------------------------------------------------------------------------
// Window attention: one warp per (window, channel-group of 24).
// Half-warp 0 handles the raw head, half-warp 1 the 5x5-avg-pooled head.
// ---------------------------------------------------------------------------
__global__ void attn_kernel(const float* __restrict__ qkv, float* __restrict__ aout)
{
    __shared__ float t [8][24][17];   // raw 24x16 tile per warp (+pad)
    __shared__ float pt[8][24][17];   // pooled tile
    __shared__ float kvs[8][2][72];   // kv[d][m] per (warp, half)

    const int w    = threadIdx.x >> 5;
    const int lane = threadIdx.x & 31;
    const int g0   = blockIdx.y * 8 + w;        // channel-group 0..31
    const int n    = blockIdx.x;                // window id
    const int b    = n / NWIN_PER_B;
    const int rem  = n - b * NWIN_PER_B;
    const int hn   = rem / 48, wn = rem - hn * 48;
    const int pixbase = (hn * 4) * HW + wn * 4;

    const float* src = qkv + (size_t)b * C_QKV * PIX + (size_t)(g0 * 24) * PIX + pixbase;

    const int p    = lane & 15;
    const int r    = p >> 2, c = p & 3;
    const int poff = r * HW + c;
    const int half = lane >> 4;

    // ---- load raw tile: 24 channels x 16 pixels
#pragma unroll
    for (int i = 0; i < 12; i++) {
        const int ch = 2 * i + half;
        t[w][ch][p] = src[(size_t)ch * PIX + poff];
    }
    __syncwarp();

    // ---- 5x5 avg pool (pad 2) inside the 4x4 window
    const int r0 = (r - 2 < 0) ? 0 : r - 2, r1 = (r + 2 > 3) ? 3 : r + 2;
    const int c0 = (c - 2 < 0) ? 0 : c - 2, c1 = (c + 2 > 3) ? 3 : c + 2;
#pragma unroll
    for (int i = 0; i < 12; i++) {
        const int ch = 2 * i + half;
        float s = 0.f;
        for (int rr = r0; rr <= r1; rr++)
            for (int cc = c0; cc <= c1; cc++)
                s += t[w][ch][rr * 4 + cc];
        pt[w][ch][p] = s * (1.0f / 25.0f);
    }
    __syncwarp();

    const float (*tile)[17] = half ? pt[w] : t[w];
    const int lh = lane & 15;

    // ---- kv[d][m] = sum_l relu(k[l][d]) * v[l][m]   (v[:,8] == 1)
    for (int j = lh; j < 72; j += 16) {
        const int d = j / 9, m = j - d * 9;
        float s = 0.f;
#pragma unroll
        for (int pp = 0; pp < 16; pp++) {
            float kd = fmaxf(tile[8 + d][pp], 0.f);
            float vm = (m < 8) ? tile[16 + m][pp] : 1.f;
            s = fmaf(kd, vm, s);
        }
        kvs[w][half][j] = s;
    }
    __syncwarp();

    // ---- out[l][m] = relu(q[l]) . kv[:,m], normalize by m==8 column
    float qv[8];
#pragma unroll
    for (int d = 0; d < 8; d++) qv[d] = fmaxf(tile[d][lh], 0.f);
    float acc[9] = {};
#pragma unroll
    for (int d = 0; d < 8; d++)
#pragma unroll
        for (int m = 0; m < 9; m++)
            acc[m] = fmaf(qv[d], kvs[w][half][d * 9 + m], acc[m]);

    const float inv = 1.f / (acc[8] + 1e-15f);
    const int rr2 = lh >> 2, cc2 = lh & 3;
    float* dst = aout + (size_t)b * C_ATT * PIX
                      + (size_t)(half * 256 + g0 * 8) * PIX
                      + pixbase + rr2 * HW + cc2;
#pragma unroll
    for (int m = 0; m < 8; m++)
        dst[(size_t)m * PIX] = acc[m] * inv;
}

// ---------------------------------------------------------------------------
extern "C" void kernel_launch(void* const* d_in, const int* in_sizes, int n_in,
                              void* d_out, int out_size)
{
    const float* x      = (const float*)d_in[0];
    const float* qkv_w  = (const float*)d_in[1];
    const float* proj_w = (const float*)d_in[2];
    const float* gamma  = (const float*)d_in[3];
    const float* beta   = (const float*)d_in[4];
    const float* mean   = (const float*)d_in[5];
    const float* var    = (const float*)d_in[6];
    float* out = (float*)d_out;

    float* qkvbuf = nullptr;
    float* attbuf = nullptr;
    cudaGetSymbolAddress((void**)&qkvbuf, g_qkv);
    cudaGetSymbolAddress((void**)&attbuf, g_att);

    // K1: qkv = W_qkv * x      (M=768, K=256)
    gemm_kernel<C_QKV, C_IN, false>
        <<<dim3(PIX / 64, C_QKV / 64, NB), 256>>>(qkv_w, x, qkvbuf,
                                                  nullptr, nullptr, nullptr, nullptr);

    // K2: window lite-MSA (raw + pooled heads)
    attn_kernel<<<dim3(NWIN, 4), 256>>>(qkvbuf, attbuf);

    // K3: y = W_proj * att, fused BN  (M=256, K=512)
    gemm_kernel<C_OUT, C_ATT, true>
        <<<dim3(PIX / 64, C_OUT / 64, NB), 256>>>(proj_w, attbuf, out,
                                                  gamma, beta, mean, var);
}

// round 10
// speedup vs baseline: 1.0035x; 1.0005x over previous
#include <cuda_runtime.h>

#define HW 192
#define PIX 36864              // 192*192
#define NB 4
#define C_IN 256
#define C_QKV 768
#define C_ATT 512
#define C_OUT 256
#define NWIN_PER_B 2304        // 48*48
#define NWIN 9216

// scratch (allocation-free rule: __device__ globals)
__device__ float g_qkv[(size_t)NB * C_QKV * PIX];
__device__ float g_att[(size_t)NB * C_ATT * PIX];

// ---------------------------------------------------------------------------
// Generic fp32 GEMM over pixels: Y[b][o][p] = sum_k W[o][k] * X[b][k][p]
// BM=64 (o), BN=64 (p), BK=16, 256 threads, 4x4 per-thread tile.
// Optional fused BN epilogue.
// ---------------------------------------------------------------------------
template <int M, int K, bool BN_EP>
__global__ void gemm_kernel(const float* __restrict__ Wm,
                            const float* __restrict__ Xg,
                            float* __restrict__ Yg,
                            const float* __restrict__ gamma,
                            const float* __restrict__ beta,
                            const float* __restrict__ mean,
                            const float* __restrict__ var)
{
    constexpr int BM = 64, BN = 64, BK = 16;
    __shared__ float As[BK][BM];
    __shared__ float Bs[BK][BN];

    const int b  = blockIdx.z;
    const int m0 = blockIdx.y * BM;
    const int n0 = blockIdx.x * BN;
    const float* X = Xg + (size_t)b * K * PIX;
    float*       Y = Yg + (size_t)b * M * PIX;

    const int tid = threadIdx.x;
    const int tx  = tid & 15;   // pixel sub-tile
    const int ty  = tid >> 4;   // channel sub-tile

    const int a_row = tid >> 2;        // m   (0..63)
    const int a_col = (tid & 3) * 4;   // k   (0,4,8,12)
    const int b_row = tid >> 4;        // k   (0..15)
    const int b_col = (tid & 15) * 4;  // n   (0..60)

    float acc[4][4] = {};

    for (int k0 = 0; k0 < K; k0 += BK) {
        float4 av = *(const float4*)&Wm[(size_t)(m0 + a_row) * K + k0 + a_col];
        As[a_col + 0][a_row] = av.x;
        As[a_col + 1][a_row] = av.y;
        As[a_col + 2][a_row] = av.z;
        As[a_col + 3][a_row] = av.w;
        *(float4*)&Bs[b_row][b_col] =
            *(const float4*)&X[(size_t)(k0 + b_row) * PIX + n0 + b_col];
        __syncthreads();

#pragma unroll
        for (int kk = 0; kk < BK; kk++) {
            float4 a4 = *(const float4*)&As[kk][ty * 4];
            float4 b4 = *(const float4*)&Bs[kk][tx * 4];
            float ar[4] = {a4.x, a4.y, a4.z, a4.w};
            float br[4] = {b4.x, b4.y, b4.z, b4.w};
#pragma unroll
            for (int i = 0; i < 4; i++)
#pragma unroll
                for (int j = 0; j < 4; j++)
                    acc[i][j] = fmaf(ar[i], br[j], acc[i][j]);
        }
        __syncthreads();
    }

#pragma unroll
    for (int i = 0; i < 4; i++) {
        const int o = m0 + ty * 4 + i;
        float sc = 1.f, sh = 0.f;
        if (BN_EP) {
            float inv = gamma[o] * rsqrtf(var[o] + 1e-5f);
            sc = inv;
            sh = beta[o] - mean[o] * inv;
        }
        float4 r;
        r.x = acc[i][0] * sc + sh;
        r.y = acc[i][1] * sc + sh;
        r.z = acc[i][2] * sc + sh;
        r.w = acc[i][3] * sc + sh;
        *(float4*)&Y[(size_t)o * PIX + n0 + tx * 4] = r;
    }
}

// ---------------------------------------------------------------------------
// Window attention: one warp per (window, channel-group of 24).
// Half-warp 0 handles the raw head, half-warp 1 the 5x5-avg-pooled head.
// ---------------------------------------------------------------------------
__global__ void attn_kernel(const float* __restrict__ qkv, float* __restrict__ aout)
{
    __shared__ float t [8][24][17];   // raw 24x16 tile per warp (+pad)
    __shared__ float pt[8][24][17];   // pooled tile
    __shared__ float kvs[8][2][72];   // kv[d][m] per (warp, half)

    const int w    = threadIdx.x >> 5;
    const int lane = threadIdx.x & 31;
    const int g0   = blockIdx.y * 8 + w;        // channel-group 0..31
    const int n    = blockIdx.x;                // window id
    const int b    = n / NWIN_PER_B;
    const int rem  = n - b * NWIN_PER_B;
    const int hn   = rem / 48, wn = rem - hn * 48;
    const int pixbase = (hn * 4) * HW + wn * 4;

    const float* src = qkv + (size_t)b * C_QKV * PIX + (size_t)(g0 * 24) * PIX + pixbase;

    const int p    = lane & 15;
    const int r    = p >> 2, c = p & 3;
    const int poff = r * HW + c;
    const int half = lane >> 4;

    // ---- load raw tile: 24 channels x 16 pixels
#pragma unroll
    for (int i = 0; i < 12; i++) {
        const int ch = 2 * i + half;
        t[w][ch][p] = src[(size_t)ch * PIX + poff];
    }
    __syncwarp();

    // ---- 5x5 avg pool (pad 2) inside the 4x4 window
    const int r0 = (r - 2 < 0) ? 0 : r - 2, r1 = (r + 2 > 3) ? 3 : r + 2;
    const int c0 = (c - 2 < 0) ? 0 : c - 2, c1 = (c + 2 > 3) ? 3 : c + 2;
#pragma unroll
    for (int i = 0; i < 12; i++) {
        const int ch = 2 * i + half;
        float s = 0.f;
        for (int rr = r0; rr <= r1; rr++)
            for (int cc = c0; cc <= c1; cc++)
                s += t[w][ch][rr * 4 + cc];
        pt[w][ch][p] = s * (1.0f / 25.0f);
    }
    __syncwarp();

    const float (*tile)[17] = half ? pt[w] : t[w];
    const int lh = lane & 15;

    // ---- kv[d][m] = sum_l relu(k[l][d]) * v[l][m]   (v[:,8] == 1)
    for (int j = lh; j < 72; j += 16) {
        const int d = j / 9, m = j - d * 9;
        float s = 0.f;
#pragma unroll
        for (int pp = 0; pp < 16; pp++) {
            float kd = fmaxf(tile[8 + d][pp], 0.f);
            float vm = (m < 8) ? tile[16 + m][pp] : 1.f;
            s = fmaf(kd, vm, s);
        }
        kvs[w][half][j] = s;
    }
    __syncwarp();

    // ---- out[l][m] = relu(q[l]) . kv[:,m], normalize by m==8 column
    float qv[8];
#pragma unroll
    for (int d = 0; d < 8; d++) qv[d] = fmaxf(tile[d][lh], 0.f);
    float acc[9] = {};
#pragma unroll
    for (int d = 0; d < 8; d++)
#pragma unroll
        for (int m = 0; m < 9; m++)
            acc[m] = fmaf(qv[d], kvs[w][half][d * 9 + m], acc[m]);

    const float inv = 1.f / (acc[8] + 1e-15f);
    const int rr2 = lh >> 2, cc2 = lh & 3;
    float* dst = aout + (size_t)b * C_ATT * PIX
                      + (size_t)(half * 256 + g0 * 8) * PIX
                      + pixbase + rr2 * HW + cc2;
#pragma unroll
    for (int m = 0; m < 8; m++)
        dst[(size_t)m * PIX] = acc[m] * inv;
}

// ---------------------------------------------------------------------------
extern "C" void kernel_launch(void* const* d_in, const int* in_sizes, int n_in,
                              void* d_out, int out_size)
{
    const float* x      = (const float*)d_in[0];
    const float* qkv_w  = (const float*)d_in[1];
    const float* proj_w = (const float*)d_in[2];
    const float* gamma  = (const float*)d_in[3];
    const float* beta   = (const float*)d_in[4];
    const float* mean   = (const float*)d_in[5];
    const float* var    = (const float*)d_in[6];
    float* out = (float*)d_out;

    float* qkvbuf = nullptr;
    float* attbuf = nullptr;
    cudaGetSymbolAddress((void**)&qkvbuf, g_qkv);
    cudaGetSymbolAddress((void**)&attbuf, g_att);

    // K1: qkv = W_qkv * x      (M=768, K=256)
    gemm_kernel<C_QKV, C_IN, false>
        <<<dim3(PIX / 64, C_QKV / 64, NB), 256>>>(qkv_w, x, qkvbuf,
                                                  nullptr, nullptr, nullptr, nullptr);

    // K2: window lite-MSA (raw + pooled heads)
    attn_kernel<<<dim3(NWIN, 4), 256>>>(qkvbuf, attbuf);

    // K3: y = W_proj * att, fused BN  (M=256, K=512)
    gemm_kernel<C_OUT, C_ATT, true>
        <<<dim3(PIX / 64, C_OUT / 64, NB), 256>>>(proj_w, attbuf, out,
                                                  gamma, beta, mean, var);
}